// round 2
// baseline (speedup 1.0000x reference)
#include <cuda_runtime.h>

#define BB 8
#define NN 4096
#define NPTS (BB*NN)
#define KK 20
#define EPS_BN 1e-5f

// ---- scratch (device globals; no allocation allowed) ----
__device__ float g_xx[NPTS];
__device__ int   g_idx[NPTS*KK];
__device__ float g_x1[NPTS*64];
__device__ float g_x2[NPTS*64];
__device__ float g_x3[NPTS*64];
__device__ float g_cat[(size_t)NPTS*192];
__device__ float g_vf [(size_t)NPTS*1024];
__device__ float g_hcat[(size_t)NPTS*1216];
__device__ float g_h7[(size_t)NPTS*512];
__device__ float g_h8[(size_t)NPTS*256];
__device__ float g_gmean[BB*1024];
__device__ float g_part[BB*1024*16];

// ---- xx = sum(x*x, -1) ----
template<int C>
__global__ __launch_bounds__(128) void xx_kernel(const float* __restrict__ x,
                                                 float* __restrict__ xx) {
    int i = blockIdx.x*128 + threadIdx.x;
    float s = 0.f;
    #pragma unroll
    for (int c = 0; c < C; ++c) { float v = x[(size_t)i*C + c]; s = fmaf(v, v, s); }
    xx[i] = s;
}

// ---- kNN: top-20 of pdist = 2*dot - xx_n - xx_m ----
template<int C>
__global__ __launch_bounds__(128) void knn_kernel(const float* __restrict__ x,
                                                  const float* __restrict__ xx,
                                                  int* __restrict__ idxout) {
    constexpr int TILE = 128;
    __shared__ float xs[TILE*C];
    __shared__ float xxs[TILE];
    int tid = threadIdx.x;
    int gpt = blockIdx.x*128 + tid;
    int b = gpt >> 12;
    const float* xb  = x  + (size_t)b*NN*C;
    const float* xxb = xx + (size_t)b*NN;

    float q[C];
    #pragma unroll
    for (int c = 0; c < C; ++c) q[c] = x[(size_t)gpt*C + c];
    float qq = xx[gpt];

    float tv[KK]; int ti[KK];
    #pragma unroll
    for (int s = 0; s < KK; ++s) { tv[s] = -3.4e38f; ti[s] = 0; }

    for (int m0 = 0; m0 < NN; m0 += TILE) {
        __syncthreads();
        for (int l = tid; l < TILE*C; l += 128) xs[l] = xb[(size_t)m0*C + l];
        if (tid < TILE) xxs[tid] = xxb[m0 + tid];
        __syncthreads();
        #pragma unroll 2
        for (int mm = 0; mm < TILE; ++mm) {
            float dot = 0.f;
            if constexpr (C % 4 == 0) {
                const float4* xr = (const float4*)(xs + mm*C);
                #pragma unroll
                for (int c4 = 0; c4 < C/4; ++c4) {
                    float4 v = xr[c4];
                    dot = fmaf(q[4*c4+0], v.x, dot);
                    dot = fmaf(q[4*c4+1], v.y, dot);
                    dot = fmaf(q[4*c4+2], v.z, dot);
                    dot = fmaf(q[4*c4+3], v.w, dot);
                }
            } else {
                #pragma unroll
                for (int c = 0; c < C; ++c) dot = fmaf(q[c], xs[mm*C + c], dot);
            }
            float v = 2.0f*dot - qq - xxs[mm];
            if (v > tv[KK-1]) {
                float cv = v; int ci = m0 + mm;
                #pragma unroll
                for (int s = 0; s < KK; ++s) {
                    if (cv > tv[s]) {
                        float t1 = tv[s]; int t2 = ti[s];
                        tv[s] = cv; ti[s] = ci; cv = t1; ci = t2;
                    }
                }
            }
        }
    }
    #pragma unroll
    for (int s = 0; s < KK; ++s) idxout[(size_t)gpt*KK + s] = ti[s];
}

// ---- fused edge-conv (1 or 2 conv-bn-lrelu) + max over k ----
template<int CIN, bool TWO>
__global__ __launch_bounds__(256) void edgeconv_kernel(
    const float* __restrict__ x, const int* __restrict__ nbr,
    const float* __restrict__ Wa, const float* __restrict__ bna,
    const float* __restrict__ Wb, const float* __restrict__ bnb,
    float* __restrict__ out)
{
    constexpr int C2 = 2*CIN;
    constexpr int GSZ0 = CIN*KK + (TWO ? 64*KK : 0) + CIN + KK;
    constexpr int GSZ  = (GSZ0 + 3) & ~3;
    extern __shared__ float sm[];
    float* Wat  = sm;                         // [C2][64]
    float* Wbt  = Wat + C2*64;                // [64][64] if TWO
    float* bnAs = Wbt + (TWO ? 4096 : 0);
    float* bnBs = bnAs + 192;
    float* grp  = bnBs + (TWO ? 192 : 0);

    int tid = threadIdx.x;
    int g = tid >> 6, o = tid & 63;

    for (int l = tid; l < 64*C2; l += 256) {
        int oo = l / C2, cc = l - oo*C2;
        Wat[cc*64 + oo] = Wa[l];
    }
    if (TWO)
        for (int l = tid; l < 4096; l += 256) Wbt[(l & 63)*64 + (l >> 6)] = Wb[l];
    if (tid < 64) {
        float ga = bna[tid], bt = bna[64+tid], mu = bna[128+tid], va = bna[192+tid];
        bnAs[tid] = ga*rsqrtf(va + EPS_BN); bnAs[64+tid] = mu; bnAs[128+tid] = bt;
    } else if (TWO && tid < 128) {
        int t = tid - 64;
        float ga = bnb[t], bt = bnb[64+t], mu = bnb[128+t], va = bnb[192+t];
        bnBs[t] = ga*rsqrtf(va + EPS_BN); bnBs[64+t] = mu; bnBs[128+t] = bt;
    }
    __syncthreads();

    float* gdiff = grp + g*GSZ;               // [CIN][KK]
    float* gh1   = gdiff + CIN*KK;            // [64][KK] if TWO
    float* gcen  = gh1 + (TWO ? 64*KK : 0);   // [CIN]
    int*   gsnb  = (int*)(gcen + CIN);        // [KK]

    float sA = bnAs[o], mA = bnAs[64+o], bA = bnAs[128+o];
    float sB = 0.f, mB = 0.f, bB = 0.f;
    if (TWO) { sB = bnBs[o]; mB = bnBs[64+o]; bB = bnBs[128+o]; }

    int base = (blockIdx.x*4 + g) * 4;
    for (int p = 0; p < 4; ++p) {
        int gpt = base + p;
        int brow = (gpt >> 12) << 12;
        float cenv = 0.f;
        if (o < CIN) { cenv = x[(size_t)gpt*CIN + o]; gcen[o] = cenv; }
        if (o < KK) gsnb[o] = nbr[(size_t)gpt*KK + o];
        __syncthreads();
        if (o < CIN) {
            #pragma unroll
            for (int j = 0; j < KK; ++j) {
                int m = gsnb[j];
                gdiff[o*KK + j] = x[((size_t)(brow + m))*CIN + o] - cenv;
            }
        }
        float cd = 0.f;
        #pragma unroll
        for (int c = 0; c < CIN; ++c) cd = fmaf(Wat[(CIN + c)*64 + o], gcen[c], cd);
        __syncthreads();

        float acc[KK];
        #pragma unroll
        for (int j = 0; j < KK; ++j) acc[j] = cd;
        #pragma unroll 4
        for (int c = 0; c < CIN; ++c) {
            float w = Wat[c*64 + o];
            const float4* dr = (const float4*)(gdiff + c*KK);
            #pragma unroll
            for (int j4 = 0; j4 < KK/4; ++j4) {
                float4 v = dr[j4];
                acc[4*j4+0] = fmaf(w, v.x, acc[4*j4+0]);
                acc[4*j4+1] = fmaf(w, v.y, acc[4*j4+1]);
                acc[4*j4+2] = fmaf(w, v.z, acc[4*j4+2]);
                acc[4*j4+3] = fmaf(w, v.w, acc[4*j4+3]);
            }
        }
        float vmax = -3.4e38f;
        if (TWO) {
            #pragma unroll
            for (int j = 0; j < KK; ++j) {
                float y = (acc[j] - mA)*sA + bA;
                y = (y >= 0.f) ? y : 0.2f*y;
                gh1[o*KK + j] = y;
            }
            __syncthreads();
            float a2[KK];
            #pragma unroll
            for (int j = 0; j < KK; ++j) a2[j] = 0.f;
            #pragma unroll 4
            for (int c = 0; c < 64; ++c) {
                float w = Wbt[c*64 + o];
                const float4* hr = (const float4*)(gh1 + c*KK);
                #pragma unroll
                for (int j4 = 0; j4 < KK/4; ++j4) {
                    float4 v = hr[j4];
                    a2[4*j4+0] = fmaf(w, v.x, a2[4*j4+0]);
                    a2[4*j4+1] = fmaf(w, v.y, a2[4*j4+1]);
                    a2[4*j4+2] = fmaf(w, v.z, a2[4*j4+2]);
                    a2[4*j4+3] = fmaf(w, v.w, a2[4*j4+3]);
                }
            }
            #pragma unroll
            for (int j = 0; j < KK; ++j) {
                float y = (a2[j] - mB)*sB + bB;
                y = (y >= 0.f) ? y : 0.2f*y;
                vmax = fmaxf(vmax, y);
            }
        } else {
            #pragma unroll
            for (int j = 0; j < KK; ++j) {
                float y = (acc[j] - mA)*sA + bA;
                y = (y >= 0.f) ? y : 0.2f*y;
                vmax = fmaxf(vmax, y);
            }
        }
        out[(size_t)gpt*64 + o] = vmax;
        __syncthreads();
    }
}

// ---- dense GEMM: out[m,n] = act(bn(sum_k A[m,k]*W[n,k])) ----
__global__ __launch_bounds__(256) void gemm_kernel(
    const float* __restrict__ A, const float* __restrict__ W,
    const float* __restrict__ bn, float* __restrict__ out,
    int M, int Ncols, int Kd, int act)
{
    __shared__ float As[8][128];
    __shared__ float Ws[8][128];
    int tid = threadIdx.x;
    int bm  = blockIdx.y*128, bn0 = blockIdx.x*128;
    int lr = tid >> 1;
    int lk = (tid & 1)*4;
    int ty = tid >> 4, tx = tid & 15;

    float acc[8][8];
    #pragma unroll
    for (int i = 0; i < 8; ++i)
        #pragma unroll
        for (int j = 0; j < 8; ++j) acc[i][j] = 0.f;

    const float* Ap = A + (size_t)(bm + lr)*Kd + lk;
    const float* Wp = W + (size_t)(bn0 + lr)*Kd + lk;

    for (int k0 = 0; k0 < Kd; k0 += 8) {
        float4 av = *(const float4*)(Ap + k0);
        float4 wv = *(const float4*)(Wp + k0);
        __syncthreads();
        As[lk+0][lr] = av.x; As[lk+1][lr] = av.y; As[lk+2][lr] = av.z; As[lk+3][lr] = av.w;
        Ws[lk+0][lr] = wv.x; Ws[lk+1][lr] = wv.y; Ws[lk+2][lr] = wv.z; Ws[lk+3][lr] = wv.w;
        __syncthreads();
        #pragma unroll
        for (int k = 0; k < 8; ++k) {
            float a[8], bb[8];
            *(float4*)(a)    = *(const float4*)&As[k][ty*8];
            *(float4*)(a+4)  = *(const float4*)&As[k][ty*8+4];
            *(float4*)(bb)   = *(const float4*)&Ws[k][tx*8];
            *(float4*)(bb+4) = *(const float4*)&Ws[k][tx*8+4];
            #pragma unroll
            for (int i = 0; i < 8; ++i)
                #pragma unroll
                for (int j = 0; j < 8; ++j) acc[i][j] = fmaf(a[i], bb[j], acc[i][j]);
        }
    }

    float sc[8], mu[8], be[8];
    #pragma unroll
    for (int j = 0; j < 8; ++j) {
        if (act) {
            int col = bn0 + tx*8 + j;
            float ga = bn[col], bt = bn[Ncols+col], m = bn[2*Ncols+col], va = bn[3*Ncols+col];
            sc[j] = ga*rsqrtf(va + EPS_BN); mu[j] = m; be[j] = bt;
        }
    }
    #pragma unroll
    for (int i = 0; i < 8; ++i) {
        int row = bm + ty*8 + i;
        float* orow = out + (size_t)row*Ncols + bn0 + tx*8;
        #pragma unroll
        for (int j = 0; j < 8; ++j) {
            float y = acc[i][j];
            if (act) { y = (y - mu[j])*sc[j] + be[j]; y = (y >= 0.f) ? y : 0.2f*y; }
            orow[j] = y;
        }
    }
}

// ---- concats ----
__global__ __launch_bounds__(256) void concat192_kernel(
    const float* __restrict__ x1, const float* __restrict__ x2,
    const float* __restrict__ x3, float* __restrict__ cat)
{
    int i = blockIdx.x*256 + threadIdx.x;
    int pt = i / 192, c = i - pt*192;
    float v;
    if (c < 64)       v = x1[(size_t)pt*64 + c];
    else if (c < 128) v = x2[(size_t)pt*64 + c - 64];
    else              v = x3[(size_t)pt*64 + c - 128];
    cat[i] = v;
}

__global__ __launch_bounds__(256) void concat1216_kernel(
    const float* __restrict__ gm, const float* __restrict__ x1,
    const float* __restrict__ x2, const float* __restrict__ x3,
    float* __restrict__ hcat)
{
    size_t i = (size_t)blockIdx.x*256 + threadIdx.x;
    int pt = (int)(i / 1216); int c = (int)(i - (size_t)pt*1216);
    int b = pt >> 12;
    float v;
    if (c < 1024)      v = gm[(b << 10) + c];
    else if (c < 1088) v = x1[(size_t)pt*64 + c - 1024];
    else if (c < 1152) v = x2[(size_t)pt*64 + c - 1088];
    else               v = x3[(size_t)pt*64 + c - 1152];
    hcat[i] = v;
}

// ---- deterministic mean over N (two-pass) ----
__global__ __launch_bounds__(256) void mean1_kernel(const float* __restrict__ vf,
                                                    float* __restrict__ part) {
    int i = blockIdx.x*256 + threadIdx.x;   // B*1024*16
    int c = i & 1023; int t = i >> 10; int b = t >> 4; int s = t & 15;
    const float* p = vf + ((size_t)(b*NN + s*256))*1024 + c;
    float sum = 0.f;
    #pragma unroll 8
    for (int n = 0; n < 256; ++n) sum += p[(size_t)n*1024];
    part[i] = sum;
}

__global__ __launch_bounds__(256) void mean2_kernel(const float* __restrict__ part,
                                                    float* __restrict__ gmean,
                                                    float* __restrict__ outg) {
    int i = blockIdx.x*256 + threadIdx.x;   // B*1024
    int b = i >> 10, c = i & 1023;
    float s = 0.f;
    #pragma unroll
    for (int t = 0; t < 16; ++t) s += part[((b*16 + t) << 10) + c];
    s *= (1.0f/NN);
    gmean[i] = s;
    outg[i] = s;
}

// ---- final 256 -> 3 projection ----
__global__ __launch_bounds__(256) void final_kernel(const float* __restrict__ h,
                                                    const float* __restrict__ W9,
                                                    float* __restrict__ out) {
    int warp = (blockIdx.x*256 + threadIdx.x) >> 5;
    int lane = threadIdx.x & 31;
    const float* hr = h + (size_t)warp*256;
    float p0 = 0.f, p1 = 0.f, p2 = 0.f;
    #pragma unroll
    for (int c0 = 0; c0 < 256; c0 += 32) {
        int c = c0 + lane;
        float hv = hr[c];
        p0 = fmaf(hv, W9[c],       p0);
        p1 = fmaf(hv, W9[256 + c], p1);
        p2 = fmaf(hv, W9[512 + c], p2);
    }
    #pragma unroll
    for (int off = 16; off; off >>= 1) {
        p0 += __shfl_down_sync(0xffffffffu, p0, off);
        p1 += __shfl_down_sync(0xffffffffu, p1, off);
        p2 += __shfl_down_sync(0xffffffffu, p2, off);
    }
    if (lane == 0) {
        out[(size_t)warp*3 + 0] = p0;
        out[(size_t)warp*3 + 1] = p1;
        out[(size_t)warp*3 + 2] = p2;
    }
}

static int ec_smem(int cin, bool two) {
    int c2 = 2*cin;
    int gsz0 = cin*KK + (two ? 64*KK : 0) + cin + KK;
    int gsz = (gsz0 + 3) & ~3;
    return (c2*64 + (two ? 4096 : 0) + 192 + (two ? 192 : 0) + 4*gsz) * 4;
}

extern "C" void kernel_launch(void* const* d_in, const int* in_sizes, int n_in,
                              void* d_out, int out_size) {
    (void)in_sizes; (void)n_in; (void)out_size;
    const float* x  = (const float*)d_in[0];
    const float* W1 = (const float*)d_in[1];
    const float* W2 = (const float*)d_in[2];
    const float* W3 = (const float*)d_in[3];
    const float* W4 = (const float*)d_in[4];
    const float* W5 = (const float*)d_in[5];
    const float* W6 = (const float*)d_in[6];
    const float* W7 = (const float*)d_in[7];
    const float* W8 = (const float*)d_in[8];
    const float* W9 = (const float*)d_in[9];
    const float* bn1 = (const float*)d_in[10];
    const float* bn2 = (const float*)d_in[11];
    const float* bn3 = (const float*)d_in[12];
    const float* bn4 = (const float*)d_in[13];
    const float* bn5 = (const float*)d_in[14];
    const float* bn6 = (const float*)d_in[15];
    const float* bn7 = (const float*)d_in[16];
    const float* bn8 = (const float*)d_in[17];
    float* outp = (float*)d_out;

    float *xx, *x1, *x2, *x3, *cat, *vf, *hcat, *h7, *h8, *gmean, *part;
    int *idx;
    cudaGetSymbolAddress((void**)&xx,  g_xx);
    cudaGetSymbolAddress((void**)&idx, g_idx);
    cudaGetSymbolAddress((void**)&x1,  g_x1);
    cudaGetSymbolAddress((void**)&x2,  g_x2);
    cudaGetSymbolAddress((void**)&x3,  g_x3);
    cudaGetSymbolAddress((void**)&cat, g_cat);
    cudaGetSymbolAddress((void**)&vf,  g_vf);
    cudaGetSymbolAddress((void**)&hcat,g_hcat);
    cudaGetSymbolAddress((void**)&h7,  g_h7);
    cudaGetSymbolAddress((void**)&h8,  g_h8);
    cudaGetSymbolAddress((void**)&gmean, g_gmean);
    cudaGetSymbolAddress((void**)&part,  g_part);

    int sm1 = ec_smem(3, true), sm2 = ec_smem(64, true), sm3 = ec_smem(64, false);
    cudaFuncSetAttribute(edgeconv_kernel<3,true>,   cudaFuncAttributeMaxDynamicSharedMemorySize, sm1);
    cudaFuncSetAttribute(edgeconv_kernel<64,true>,  cudaFuncAttributeMaxDynamicSharedMemorySize, sm2);
    cudaFuncSetAttribute(edgeconv_kernel<64,false>, cudaFuncAttributeMaxDynamicSharedMemorySize, sm3);

    // stage 1
    xx_kernel<3><<<NPTS/128, 128>>>(x, xx);
    knn_kernel<3><<<NPTS/128, 128>>>(x, xx, idx);
    edgeconv_kernel<3,true><<<NPTS/16, 256, sm1>>>(x, idx, W1, bn1, W2, bn2, x1);
    // stage 2
    xx_kernel<64><<<NPTS/128, 128>>>(x1, xx);
    knn_kernel<64><<<NPTS/128, 128>>>(x1, xx, idx);
    edgeconv_kernel<64,true><<<NPTS/16, 256, sm2>>>(x1, idx, W3, bn3, W4, bn4, x2);
    // stage 3
    xx_kernel<64><<<NPTS/128, 128>>>(x2, xx);
    knn_kernel<64><<<NPTS/128, 128>>>(x2, xx, idx);
    edgeconv_kernel<64,false><<<NPTS/16, 256, sm3>>>(x2, idx, W5, bn5, nullptr, nullptr, x3);
    // global feature
    concat192_kernel<<<NPTS*192/256, 256>>>(x1, x2, x3, cat);
    gemm_kernel<<<dim3(1024/128, NPTS/128), 256>>>(cat, W6, bn6, vf, NPTS, 1024, 192, 1);
    mean1_kernel<<<BB*1024*16/256, 256>>>(vf, part);
    mean2_kernel<<<BB*1024/256, 256>>>(part, gmean, outp);          // g -> out[0:8192]
    // decoder
    concat1216_kernel<<<(int)((size_t)NPTS*1216/256), 256>>>(gmean, x1, x2, x3, hcat);
    gemm_kernel<<<dim3(512/128, NPTS/128), 256>>>(hcat, W7, bn7, h7, NPTS, 512, 1216, 1);
    gemm_kernel<<<dim3(256/128, NPTS/128), 256>>>(h7, W8, bn8, h8, NPTS, 256, 512, 1);
    final_kernel<<<NPTS/8, 256>>>(h8, W9, outp + BB*1024);          // out -> out[8192:]
}

// round 3
// speedup vs baseline: 1.2323x; 1.2323x over previous
#include <cuda_runtime.h>

#define BB 8
#define NN 4096
#define NPTS (BB*NN)
#define KK 20
#define EPS_BN 1e-5f

// ---- scratch (device globals; no allocation allowed) ----
__device__ float g_xx[NPTS];
__device__ int   g_idx[NPTS*KK];
__device__ float g_x1[NPTS*64];
__device__ float g_x2[NPTS*64];
__device__ float g_x3[NPTS*64];
__device__ float g_cat[(size_t)NPTS*192];
__device__ float g_vf [(size_t)NPTS*1024];
__device__ float g_h7[(size_t)NPTS*512];
__device__ float g_h8[(size_t)NPTS*256];
__device__ float g_gmean[BB*1024];
__device__ float g_part[BB*1024*16];
__device__ float g_b7[BB*512];

// ---- xx = sum(x*x, -1) ----
template<int C>
__global__ __launch_bounds__(128) void xx_kernel(const float* __restrict__ x,
                                                 float* __restrict__ xx) {
    int i = blockIdx.x*128 + threadIdx.x;
    float s = 0.f;
    #pragma unroll
    for (int c = 0; c < C; ++c) { float v = x[(size_t)i*C + c]; s = fmaf(v, v, s); }
    xx[i] = s;
}

// ---- kNN: top-20 of pdist = 2*dot - xx_n - xx_m ----
template<int C>
__global__ __launch_bounds__(128) void knn_kernel(const float* __restrict__ x,
                                                  const float* __restrict__ xx,
                                                  int* __restrict__ idxout) {
    constexpr int TILE = 128;
    __shared__ float xs[TILE*C];
    __shared__ float xxs[TILE];
    int tid = threadIdx.x;
    int gpt = blockIdx.x*128 + tid;
    int b = gpt >> 12;
    const float* xb  = x  + (size_t)b*NN*C;
    const float* xxb = xx + (size_t)b*NN;

    float q[C];
    #pragma unroll
    for (int c = 0; c < C; ++c) q[c] = x[(size_t)gpt*C + c];
    float qq = xx[gpt];

    float tv[KK]; int ti[KK];
    #pragma unroll
    for (int s = 0; s < KK; ++s) { tv[s] = -3.4e38f; ti[s] = 0; }

    for (int m0 = 0; m0 < NN; m0 += TILE) {
        __syncthreads();
        for (int l = tid; l < TILE*C; l += 128) xs[l] = xb[(size_t)m0*C + l];
        if (tid < TILE) xxs[tid] = xxb[m0 + tid];
        __syncthreads();
        #pragma unroll 2
        for (int mm = 0; mm < TILE; ++mm) {
            float dot = 0.f;
            if constexpr (C % 4 == 0) {
                const float4* xr = (const float4*)(xs + mm*C);
                #pragma unroll
                for (int c4 = 0; c4 < C/4; ++c4) {
                    float4 v = xr[c4];
                    dot = fmaf(q[4*c4+0], v.x, dot);
                    dot = fmaf(q[4*c4+1], v.y, dot);
                    dot = fmaf(q[4*c4+2], v.z, dot);
                    dot = fmaf(q[4*c4+3], v.w, dot);
                }
            } else {
                #pragma unroll
                for (int c = 0; c < C; ++c) dot = fmaf(q[c], xs[mm*C + c], dot);
            }
            float v = 2.0f*dot - qq - xxs[mm];
            if (v > tv[KK-1]) {
                float cv = v; int ci = m0 + mm;
                #pragma unroll
                for (int s = 0; s < KK; ++s) {
                    if (cv > tv[s]) {
                        float t1 = tv[s]; int t2 = ti[s];
                        tv[s] = cv; ti[s] = ci; cv = t1; ci = t2;
                    }
                }
            }
        }
    }
    #pragma unroll
    for (int s = 0; s < KK; ++s) idxout[(size_t)gpt*KK + s] = ti[s];
}

// ---- fused edge-conv (1 or 2 conv-bn-lrelu) + max over k ----
template<int CIN, bool TWO>
__global__ __launch_bounds__(256) void edgeconv_kernel(
    const float* __restrict__ x, const int* __restrict__ nbr,
    const float* __restrict__ Wa, const float* __restrict__ bna,
    const float* __restrict__ Wb, const float* __restrict__ bnb,
    float* __restrict__ out)
{
    constexpr int C2 = 2*CIN;
    constexpr int GSZ0 = CIN*KK + (TWO ? 64*KK : 0) + CIN + KK;
    constexpr int GSZ  = (GSZ0 + 3) & ~3;
    extern __shared__ float sm[];
    float* Wat  = sm;                         // [C2][64]
    float* Wbt  = Wat + C2*64;                // [64][64] if TWO
    float* bnAs = Wbt + (TWO ? 4096 : 0);
    float* bnBs = bnAs + 192;
    float* grp  = bnBs + (TWO ? 192 : 0);

    int tid = threadIdx.x;
    int g = tid >> 6, o = tid & 63;

    for (int l = tid; l < 64*C2; l += 256) {
        int oo = l / C2, cc = l - oo*C2;
        Wat[cc*64 + oo] = Wa[l];
    }
    if (TWO)
        for (int l = tid; l < 4096; l += 256) Wbt[(l & 63)*64 + (l >> 6)] = Wb[l];
    if (tid < 64) {
        float ga = bna[tid], bt = bna[64+tid], mu = bna[128+tid], va = bna[192+tid];
        bnAs[tid] = ga*rsqrtf(va + EPS_BN); bnAs[64+tid] = mu; bnAs[128+tid] = bt;
    } else if (TWO && tid < 128) {
        int t = tid - 64;
        float ga = bnb[t], bt = bnb[64+t], mu = bnb[128+t], va = bnb[192+t];
        bnBs[t] = ga*rsqrtf(va + EPS_BN); bnBs[64+t] = mu; bnBs[128+t] = bt;
    }
    __syncthreads();

    float* gdiff = grp + g*GSZ;               // [CIN][KK]
    float* gh1   = gdiff + CIN*KK;            // [64][KK] if TWO
    float* gcen  = gh1 + (TWO ? 64*KK : 0);   // [CIN]
    int*   gsnb  = (int*)(gcen + CIN);        // [KK]

    float sA = bnAs[o], mA = bnAs[64+o], bA = bnAs[128+o];
    float sB = 0.f, mB = 0.f, bB = 0.f;
    if (TWO) { sB = bnBs[o]; mB = bnBs[64+o]; bB = bnBs[128+o]; }

    int base = (blockIdx.x*4 + g) * 4;
    for (int p = 0; p < 4; ++p) {
        int gpt = base + p;
        int brow = (gpt >> 12) << 12;
        float cenv = 0.f;
        if (o < CIN) { cenv = x[(size_t)gpt*CIN + o]; gcen[o] = cenv; }
        if (o < KK) gsnb[o] = nbr[(size_t)gpt*KK + o];
        __syncthreads();
        if (o < CIN) {
            #pragma unroll
            for (int j = 0; j < KK; ++j) {
                int m = gsnb[j];
                gdiff[o*KK + j] = x[((size_t)(brow + m))*CIN + o] - cenv;
            }
        }
        float cd = 0.f;
        #pragma unroll
        for (int c = 0; c < CIN; ++c) cd = fmaf(Wat[(CIN + c)*64 + o], gcen[c], cd);
        __syncthreads();

        float acc[KK];
        #pragma unroll
        for (int j = 0; j < KK; ++j) acc[j] = cd;
        #pragma unroll 4
        for (int c = 0; c < CIN; ++c) {
            float w = Wat[c*64 + o];
            const float4* dr = (const float4*)(gdiff + c*KK);
            #pragma unroll
            for (int j4 = 0; j4 < KK/4; ++j4) {
                float4 v = dr[j4];
                acc[4*j4+0] = fmaf(w, v.x, acc[4*j4+0]);
                acc[4*j4+1] = fmaf(w, v.y, acc[4*j4+1]);
                acc[4*j4+2] = fmaf(w, v.z, acc[4*j4+2]);
                acc[4*j4+3] = fmaf(w, v.w, acc[4*j4+3]);
            }
        }
        float vmax = -3.4e38f;
        if (TWO) {
            #pragma unroll
            for (int j = 0; j < KK; ++j) {
                float y = (acc[j] - mA)*sA + bA;
                y = (y >= 0.f) ? y : 0.2f*y;
                gh1[o*KK + j] = y;
            }
            __syncthreads();
            float a2[KK];
            #pragma unroll
            for (int j = 0; j < KK; ++j) a2[j] = 0.f;
            #pragma unroll 4
            for (int c = 0; c < 64; ++c) {
                float w = Wbt[c*64 + o];
                const float4* hr = (const float4*)(gh1 + c*KK);
                #pragma unroll
                for (int j4 = 0; j4 < KK/4; ++j4) {
                    float4 v = hr[j4];
                    a2[4*j4+0] = fmaf(w, v.x, a2[4*j4+0]);
                    a2[4*j4+1] = fmaf(w, v.y, a2[4*j4+1]);
                    a2[4*j4+2] = fmaf(w, v.z, a2[4*j4+2]);
                    a2[4*j4+3] = fmaf(w, v.w, a2[4*j4+3]);
                }
            }
            #pragma unroll
            for (int j = 0; j < KK; ++j) {
                float y = (a2[j] - mB)*sB + bB;
                y = (y >= 0.f) ? y : 0.2f*y;
                vmax = fmaxf(vmax, y);
            }
        } else {
            #pragma unroll
            for (int j = 0; j < KK; ++j) {
                float y = (acc[j] - mA)*sA + bA;
                y = (y >= 0.f) ? y : 0.2f*y;
                vmax = fmaxf(vmax, y);
            }
        }
        out[(size_t)gpt*64 + o] = vmax;
        __syncthreads();
    }
}

// ---- dense GEMM: out[m,n] = act(bn(bias[b,n] + sum_k A[m,k]*W[n,k])) ----
__global__ __launch_bounds__(256) void gemm_kernel(
    const float* __restrict__ A, int lda,
    const float* __restrict__ W, int ldw,
    const float* __restrict__ bn, const float* __restrict__ bias,
    float* __restrict__ out, int Ncols, int Kd, int act)
{
    __shared__ float As[8][128];
    __shared__ float Ws[8][128];
    int tid = threadIdx.x;
    int bm  = blockIdx.y*128, bn0 = blockIdx.x*128;
    int lr = tid >> 1;
    int lk = (tid & 1)*4;
    int ty = tid >> 4, tx = tid & 15;

    float acc[8][8];
    #pragma unroll
    for (int i = 0; i < 8; ++i)
        #pragma unroll
        for (int j = 0; j < 8; ++j) acc[i][j] = 0.f;

    const float* Ap = A + (size_t)(bm + lr)*lda + lk;
    const float* Wp = W + (size_t)(bn0 + lr)*ldw + lk;

    for (int k0 = 0; k0 < Kd; k0 += 8) {
        float4 av = *(const float4*)(Ap + k0);
        float4 wv = *(const float4*)(Wp + k0);
        __syncthreads();
        As[lk+0][lr] = av.x; As[lk+1][lr] = av.y; As[lk+2][lr] = av.z; As[lk+3][lr] = av.w;
        Ws[lk+0][lr] = wv.x; Ws[lk+1][lr] = wv.y; Ws[lk+2][lr] = wv.z; Ws[lk+3][lr] = wv.w;
        __syncthreads();
        #pragma unroll
        for (int k = 0; k < 8; ++k) {
            float a[8], bb[8];
            *(float4*)(a)    = *(const float4*)&As[k][ty*8];
            *(float4*)(a+4)  = *(const float4*)&As[k][ty*8+4];
            *(float4*)(bb)   = *(const float4*)&Ws[k][tx*8];
            *(float4*)(bb+4) = *(const float4*)&Ws[k][tx*8+4];
            #pragma unroll
            for (int i = 0; i < 8; ++i)
                #pragma unroll
                for (int j = 0; j < 8; ++j) acc[i][j] = fmaf(a[i], bb[j], acc[i][j]);
        }
    }

    float sc[8], mu[8], be[8], bv[8];
    #pragma unroll
    for (int j = 0; j < 8; ++j) {
        int col = bn0 + tx*8 + j;
        if (act) {
            float ga = bn[col], bt = bn[Ncols+col], m = bn[2*Ncols+col], va = bn[3*Ncols+col];
            sc[j] = ga*rsqrtf(va + EPS_BN); mu[j] = m; be[j] = bt;
        }
        bv[j] = bias ? bias[(bm >> 12)*Ncols + col] : 0.f;
    }
    #pragma unroll
    for (int i = 0; i < 8; ++i) {
        int row = bm + ty*8 + i;
        float* orow = out + (size_t)row*Ncols + bn0 + tx*8;
        #pragma unroll
        for (int j = 0; j < 8; ++j) {
            float y = acc[i][j] + bv[j];
            if (act) { y = (y - mu[j])*sc[j] + be[j]; y = (y >= 0.f) ? y : 0.2f*y; }
            orow[j] = y;
        }
    }
}

// ---- concat [x1|x2|x3] -> 192 ----
__global__ __launch_bounds__(256) void concat192_kernel(
    const float* __restrict__ x1, const float* __restrict__ x2,
    const float* __restrict__ x3, float* __restrict__ cat)
{
    int i = blockIdx.x*256 + threadIdx.x;
    int pt = i / 192, c = i - pt*192;
    float v;
    if (c < 64)       v = x1[(size_t)pt*64 + c];
    else if (c < 128) v = x2[(size_t)pt*64 + c - 64];
    else              v = x3[(size_t)pt*64 + c - 128];
    cat[i] = v;
}

// ---- deterministic mean over N (two-pass) ----
__global__ __launch_bounds__(256) void mean1_kernel(const float* __restrict__ vf,
                                                    float* __restrict__ part) {
    int i = blockIdx.x*256 + threadIdx.x;   // B*1024*16
    int c = i & 1023; int t = i >> 10; int b = t >> 4; int s = t & 15;
    const float* p = vf + ((size_t)(b*NN + s*256))*1024 + c;
    float sum = 0.f;
    #pragma unroll 8
    for (int n = 0; n < 256; ++n) sum += p[(size_t)n*1024];
    part[i] = sum;
}

__global__ __launch_bounds__(256) void mean2_kernel(const float* __restrict__ part,
                                                    float* __restrict__ gmean,
                                                    float* __restrict__ outg) {
    int i = blockIdx.x*256 + threadIdx.x;   // B*1024
    int b = i >> 10, c = i & 1023;
    float s = 0.f;
    #pragma unroll
    for (int t = 0; t < 16; ++t) s += part[((b*16 + t) << 10) + c];
    s *= (1.0f/NN);
    gmean[i] = s;
    outg[i] = s;
}

// ---- b7[b,o] = sum_{c<1024} W7[o,c] * g[b,c]  (per-batch constant slab of W7 GEMM) ----
__global__ __launch_bounds__(256) void bias7_kernel(const float* __restrict__ gm,
                                                    const float* __restrict__ W7,
                                                    float* __restrict__ b7) {
    int w = (blockIdx.x*256 + threadIdx.x) >> 5;   // 4096 warps: b*512+o
    int lane = threadIdx.x & 31;
    int b = w >> 9, o = w & 511;
    const float* gr = gm + (b << 10);
    const float* wr = W7 + (size_t)o*1216;
    float s = 0.f;
    #pragma unroll 4
    for (int c = lane; c < 1024; c += 32) s = fmaf(wr[c], gr[c], s);
    #pragma unroll
    for (int off = 16; off; off >>= 1) s += __shfl_down_sync(0xffffffffu, s, off);
    if (lane == 0) b7[(b << 9) + o] = s;
}

// ---- final 256 -> 3 projection ----
__global__ __launch_bounds__(256) void final_kernel(const float* __restrict__ h,
                                                    const float* __restrict__ W9,
                                                    float* __restrict__ out) {
    int warp = (blockIdx.x*256 + threadIdx.x) >> 5;
    int lane = threadIdx.x & 31;
    const float* hr = h + (size_t)warp*256;
    float p0 = 0.f, p1 = 0.f, p2 = 0.f;
    #pragma unroll
    for (int c0 = 0; c0 < 256; c0 += 32) {
        int c = c0 + lane;
        float hv = hr[c];
        p0 = fmaf(hv, W9[c],       p0);
        p1 = fmaf(hv, W9[256 + c], p1);
        p2 = fmaf(hv, W9[512 + c], p2);
    }
    #pragma unroll
    for (int off = 16; off; off >>= 1) {
        p0 += __shfl_down_sync(0xffffffffu, p0, off);
        p1 += __shfl_down_sync(0xffffffffu, p1, off);
        p2 += __shfl_down_sync(0xffffffffu, p2, off);
    }
    if (lane == 0) {
        out[(size_t)warp*3 + 0] = p0;
        out[(size_t)warp*3 + 1] = p1;
        out[(size_t)warp*3 + 2] = p2;
    }
}

static int ec_smem(int cin, bool two) {
    int c2 = 2*cin;
    int gsz0 = cin*KK + (two ? 64*KK : 0) + cin + KK;
    int gsz = (gsz0 + 3) & ~3;
    return (c2*64 + (two ? 4096 : 0) + 192 + (two ? 192 : 0) + 4*gsz) * 4;
}

extern "C" void kernel_launch(void* const* d_in, const int* in_sizes, int n_in,
                              void* d_out, int out_size) {
    (void)in_sizes; (void)n_in; (void)out_size;
    const float* x  = (const float*)d_in[0];
    const float* W1 = (const float*)d_in[1];
    const float* W2 = (const float*)d_in[2];
    const float* W3 = (const float*)d_in[3];
    const float* W4 = (const float*)d_in[4];
    const float* W5 = (const float*)d_in[5];
    const float* W6 = (const float*)d_in[6];
    const float* W7 = (const float*)d_in[7];
    const float* W8 = (const float*)d_in[8];
    const float* W9 = (const float*)d_in[9];
    const float* bn1 = (const float*)d_in[10];
    const float* bn2 = (const float*)d_in[11];
    const float* bn3 = (const float*)d_in[12];
    const float* bn4 = (const float*)d_in[13];
    const float* bn5 = (const float*)d_in[14];
    const float* bn6 = (const float*)d_in[15];
    const float* bn7 = (const float*)d_in[16];
    const float* bn8 = (const float*)d_in[17];
    float* outp = (float*)d_out;

    float *xx, *x1, *x2, *x3, *cat, *vf, *h7, *h8, *gmean, *part, *b7;
    int *idx;
    cudaGetSymbolAddress((void**)&xx,  g_xx);
    cudaGetSymbolAddress((void**)&idx, g_idx);
    cudaGetSymbolAddress((void**)&x1,  g_x1);
    cudaGetSymbolAddress((void**)&x2,  g_x2);
    cudaGetSymbolAddress((void**)&x3,  g_x3);
    cudaGetSymbolAddress((void**)&cat, g_cat);
    cudaGetSymbolAddress((void**)&vf,  g_vf);
    cudaGetSymbolAddress((void**)&h7,  g_h7);
    cudaGetSymbolAddress((void**)&h8,  g_h8);
    cudaGetSymbolAddress((void**)&gmean, g_gmean);
    cudaGetSymbolAddress((void**)&part,  g_part);
    cudaGetSymbolAddress((void**)&b7,  g_b7);

    int sm1 = ec_smem(3, true), sm2 = ec_smem(64, true), sm3 = ec_smem(64, false);
    cudaFuncSetAttribute(edgeconv_kernel<3,true>,   cudaFuncAttributeMaxDynamicSharedMemorySize, sm1);
    cudaFuncSetAttribute(edgeconv_kernel<64,true>,  cudaFuncAttributeMaxDynamicSharedMemorySize, sm2);
    cudaFuncSetAttribute(edgeconv_kernel<64,false>, cudaFuncAttributeMaxDynamicSharedMemorySize, sm3);

    // stage 1
    xx_kernel<3><<<NPTS/128, 128>>>(x, xx);
    knn_kernel<3><<<NPTS/128, 128>>>(x, xx, idx);
    edgeconv_kernel<3,true><<<NPTS/16, 256, sm1>>>(x, idx, W1, bn1, W2, bn2, x1);
    // stage 2
    xx_kernel<64><<<NPTS/128, 128>>>(x1, xx);
    knn_kernel<64><<<NPTS/128, 128>>>(x1, xx, idx);
    edgeconv_kernel<64,true><<<NPTS/16, 256, sm2>>>(x1, idx, W3, bn3, W4, bn4, x2);
    // stage 3
    xx_kernel<64><<<NPTS/128, 128>>>(x2, xx);
    knn_kernel<64><<<NPTS/128, 128>>>(x2, xx, idx);
    edgeconv_kernel<64,false><<<NPTS/16, 256, sm3>>>(x2, idx, W5, bn5, nullptr, nullptr, x3);
    // global feature
    concat192_kernel<<<NPTS*192/256, 256>>>(x1, x2, x3, cat);
    gemm_kernel<<<dim3(1024/128, NPTS/128), 256>>>(cat, 192, W6, 192, bn6, nullptr, vf, 1024, 192, 1);
    mean1_kernel<<<BB*1024*16/256, 256>>>(vf, part);
    mean2_kernel<<<BB*1024/256, 256>>>(part, gmean, outp);          // g -> out[0:8192]
    // decoder: W7·[g;x1;x2;x3] = (W7[:, :1024]·g) + (W7[:,1024:]·cat)
    bias7_kernel<<<512, 256>>>(gmean, W7, b7);
    gemm_kernel<<<dim3(512/128, NPTS/128), 256>>>(cat, 192, W7 + 1024, 1216, bn7, b7, h7, 512, 192, 1);
    gemm_kernel<<<dim3(256/128, NPTS/128), 256>>>(h7, 512, W8, 512, bn8, nullptr, h8, 256, 512, 1);
    final_kernel<<<NPTS/8, 256>>>(h8, W9, outp + BB*1024);          // out -> out[8192:]
}